// round 3
// baseline (speedup 1.0000x reference)
#include <cuda_runtime.h>
#include <cuda_bf16.h>
#include <stdint.h>

#define N_NODES 100000
#define N_EDGES 3200000
#define TOT_EDGES (N_EDGES + N_NODES)
#define F_IN 256
#define HID 64
#define C_OUT 2
#define G_GRAPHS 128

#define SCAN_BLK 1024
#define SCAN_NB ((N_NODES + SCAN_BLK - 1) / SCAN_BLK)

// ---------------- scratch: __device__ globals, referenced directly ----------------
__device__ float g_hx[(size_t)N_NODES * HID];     // GEMM output buffer
__device__ float g_h [(size_t)N_NODES * HID];     // aggregated / layer output
__device__ float g_isq[N_NODES];
__device__ int   g_deg[N_NODES];
__device__ int   g_rowptr[N_NODES + 1];
__device__ int   g_cursor[N_NODES];
__device__ int   g_eidx[TOT_EDGES];
__device__ int   g_bsum[SCAN_NB + 1];
__device__ float g_pool[G_GRAPHS * HID];
__device__ float g_pcnt[G_GRAPHS];
__device__ int   g_is64;                          // 1 if index dtype is int64

// ---------------- dtype detection: odd 32-bit words all zero <=> int64 ----------------
__global__ void k_detect(const int* __restrict__ ei_raw) {
    __shared__ int s_or[256];
    int tid = threadIdx.x;
    int acc = 0;
    // sample 8192 odd-position words from the first part of the buffer
    // (int32 layout: these are random node indices; int64 layout: high words == 0)
#pragma unroll
    for (int i = 0; i < 32; i++) {
        int w = 2 * (tid + i * 256) + 1;          // odd indices < 16384 < 2*E
        acc |= ei_raw[w];
    }
    s_or[tid] = acc;
    __syncthreads();
    for (int off = 128; off > 0; off >>= 1) {
        if (tid < off) s_or[tid] |= s_or[tid + off];
        __syncthreads();
    }
    if (tid == 0) g_is64 = (s_or[0] == 0) ? 1 : 0;
}

// flag-dispatched index load (uniform branch; g_is64 L1-cached)
__device__ __forceinline__ int ld_idx(const void* p, size_t i) {
    if (g_is64) return (int)((const long long*)p)[i];
    return ((const int*)p)[i];
}

// ---------------- init: deg=1 (self loop), pool=0 ----------------
__global__ void k_init() {
    int i = blockIdx.x * blockDim.x + threadIdx.x;
    if (i < N_NODES) g_deg[i] = 1;
    if (i < G_GRAPHS * HID) g_pool[i] = 0.f;
    if (i < G_GRAPHS) g_pcnt[i] = 0.f;
}

// ---------------- degree histogram over dst ----------------
__global__ void k_deg(const void* __restrict__ ei) {
    int e = blockIdx.x * blockDim.x + threadIdx.x;
    if (e >= N_EDGES) return;
    int d = ld_idx(ei, (size_t)N_EDGES + e);
    atomicAdd(&g_deg[d], 1);
}

// ---------------- scan phase 1: per-block inclusive scan ----------------
__global__ void k_scan1() {
    __shared__ int s[SCAN_BLK];
    int tid = threadIdx.x;
    int i = blockIdx.x * SCAN_BLK + tid;
    int v = (i < N_NODES) ? g_deg[i] : 0;
    s[tid] = v;
    __syncthreads();
    for (int off = 1; off < SCAN_BLK; off <<= 1) {
        int t = (tid >= off) ? s[tid - off] : 0;
        __syncthreads();
        s[tid] += t;
        __syncthreads();
    }
    if (i < N_NODES) g_cursor[i] = s[tid];        // tmp: inclusive within block
    if (tid == SCAN_BLK - 1) g_bsum[blockIdx.x] = s[tid];
}

// ---------------- scan phase 2: scan block sums (tiny) ----------------
__global__ void k_scan2() {
    int running = 0;
    for (int b = 0; b < SCAN_NB; b++) {
        int t = g_bsum[b];
        g_bsum[b] = running;
        running += t;
    }
    g_rowptr[N_NODES] = running;   // == TOT_EDGES
}

// ---------------- scan phase 3: finalize rowptr/cursor + isq ----------------
__global__ void k_scan3() {
    int i = blockIdx.x * blockDim.x + threadIdx.x;
    if (i >= N_NODES) return;
    int incl = g_cursor[i] + g_bsum[i / SCAN_BLK];
    g_rowptr[i + 1] = incl;
    int d = g_deg[i];
    g_cursor[i] = incl - d;        // exclusive prefix = fill cursor
    g_isq[i] = rsqrtf((float)d);   // deg >= 1 always (self loop)
    if (i == 0) g_rowptr[0] = 0;
}

// ---------------- fill CSR edge list (incl. self loops) ----------------
__global__ void k_fill(const void* __restrict__ ei) {
    int t = blockIdx.x * blockDim.x + threadIdx.x;
    if (t >= TOT_EDGES) return;
    int s, d;
    if (t < N_EDGES) {
        s = ld_idx(ei, t);
        d = ld_idx(ei, (size_t)N_EDGES + t);
    } else {
        s = d = t - N_EDGES;
    }
    int pos = atomicAdd(&g_cursor[d], 1);
    g_eidx[pos] = s;
}

// ---------------- dense GEMM: g_hx[N,64] = X[N,K] @ W[K,64] ----------------
template <int K, bool FROM_G>
__global__ void k_gemm(const float* __restrict__ Xin, const float* __restrict__ W) {
    __shared__ float sW[32 * 64];        // 8 KB
    __shared__ float sX[256 * 33];       // 33.8 KB (padded, conflict-free)
    const float* X = FROM_G ? (const float*)g_h : Xin;
    int tid = threadIdx.x;
    int nodeBase = blockIdx.x * 256;
    int node = nodeBase + tid;

    float acc[64];
#pragma unroll
    for (int j = 0; j < 64; j++) acc[j] = 0.f;

    for (int kk = 0; kk < K; kk += 32) {
#pragma unroll
        for (int i = 0; i < 8; i++) {
            int idx = tid + i * 256;
            sW[idx] = W[kk * 64 + idx];
        }
#pragma unroll
        for (int i = 0; i < 32; i++) {
            int idx = tid + i * 256;
            int nl = idx >> 5, kl = idx & 31;
            int n = nodeBase + nl;
            sX[nl * 33 + kl] = (n < N_NODES) ? X[(size_t)n * K + kk + kl] : 0.f;
        }
        __syncthreads();
#pragma unroll 4
        for (int k = 0; k < 32; k++) {
            float xv = sX[tid * 33 + k];
            const float4* w4 = (const float4*)&sW[k * 64];
#pragma unroll
            for (int j = 0; j < 16; j++) {
                float4 w = w4[j];
                acc[4 * j + 0] += xv * w.x;
                acc[4 * j + 1] += xv * w.y;
                acc[4 * j + 2] += xv * w.z;
                acc[4 * j + 3] += xv * w.w;
            }
        }
        __syncthreads();
    }
    if (node < N_NODES) {
        float4* o4 = (float4*)&g_hx[(size_t)node * 64];
#pragma unroll
        for (int j = 0; j < 16; j++)
            o4[j] = make_float4(acc[4 * j], acc[4 * j + 1], acc[4 * j + 2], acc[4 * j + 3]);
    }
}

// ---------------- pull aggregation: warp per node, L2-resident gather ----------------
__global__ void k_agg(const float* __restrict__ bias) {
    int gt = blockIdx.x * blockDim.x + threadIdx.x;
    int node = gt >> 5;
    int lane = gt & 31;
    if (node >= N_NODES) return;

    int r0 = g_rowptr[node];
    int r1 = g_rowptr[node + 1];
    const float2* h2 = (const float2*)g_hx;

    float ax = 0.f, ay = 0.f;
    for (int e = r0; e < r1; e++) {
        int s = g_eidx[e];            // broadcast load
        float w = g_isq[s];           // broadcast load
        float2 v = h2[(size_t)s * 32 + lane];   // coalesced 256B/warp
        ax += w * v.x;
        ay += w * v.y;
    }
    float wd = g_isq[node];
    float bx = bias[2 * lane + 0];
    float by = bias[2 * lane + 1];
    float2 o;
    o.x = fmaxf(ax * wd + bx, 0.f);
    o.y = fmaxf(ay * wd + by, 0.f);
    ((float2*)g_h)[(size_t)node * 32 + lane] = o;
}

// ---------------- global mean-pool accumulation (reads g_h) ----------------
__global__ void k_pool(const void* __restrict__ batch) {
    int gt = blockIdx.x * blockDim.x + threadIdx.x;
    int node = gt >> 5;
    int lane = gt & 31;
    if (node >= N_NODES) return;
    int g = ld_idx(batch, node);
    float2 v = ((const float2*)g_h)[(size_t)node * 32 + lane];
    atomicAdd(&g_pool[g * 64 + 2 * lane + 0], v.x);
    atomicAdd(&g_pool[g * 64 + 2 * lane + 1], v.y);
    if (lane == 0) atomicAdd(&g_pcnt[g], 1.f);
}

// ---------------- final FC ----------------
__global__ void k_fc(const float* __restrict__ fcW, const float* __restrict__ fcb,
                     float* __restrict__ out) {
    int g = threadIdx.x;
    if (g >= G_GRAPHS) return;
    float cnt = g_pcnt[g];
    float inv = 1.f / fmaxf(cnt, 1.f);
    float a0 = fcb[0], a1 = fcb[1];
#pragma unroll
    for (int h = 0; h < 64; h++) {
        float p = g_pool[g * 64 + h] * inv;
        a0 += p * fcW[h * 2 + 0];
        a1 += p * fcW[h * 2 + 1];
    }
    out[g * 2 + 0] = a0;
    out[g * 2 + 1] = a1;
}

// ---------------- launch: pure kernel launches, no other API ----------------
extern "C" void kernel_launch(void* const* d_in, const int* in_sizes, int n_in,
                              void* d_out, int out_size) {
    const float* x    = (const float*)d_in[0];
    const void*  ei   = d_in[1];
    const void*  bat  = d_in[2];
    const float* W1   = (const float*)d_in[3];
    const float* b1   = (const float*)d_in[4];
    const float* W2   = (const float*)d_in[5];
    const float* b2   = (const float*)d_in[6];
    const float* fcW  = (const float*)d_in[7];
    const float* fcb  = (const float*)d_in[8];
    float* out = (float*)d_out;

    const int TPB = 256;
    int gN   = (N_NODES + TPB - 1) / TPB;
    int gE   = (N_EDGES + TPB - 1) / TPB;
    int gTOT = (TOT_EDGES + TPB - 1) / TPB;
    int gW   = (N_NODES * 32 + TPB - 1) / TPB;

    k_detect<<<1, 256>>>((const int*)ei);
    k_init<<<gN, TPB>>>();
    k_deg<<<gE, TPB>>>(ei);
    k_scan1<<<SCAN_NB, SCAN_BLK>>>();
    k_scan2<<<1, 1>>>();
    k_scan3<<<gN, TPB>>>();
    k_fill<<<gTOT, TPB>>>(ei);

    k_gemm<F_IN, false><<<gN, TPB>>>(x, W1);         // g_hx = x @ W1
    k_agg<<<gW, TPB>>>(b1);                          // g_h = relu(agg + b1)
    k_gemm<HID, true><<<gN, TPB>>>(nullptr, W2);     // g_hx = g_h @ W2
    k_agg<<<gW, TPB>>>(b2);                          // g_h = relu(agg + b2)

    k_pool<<<gW, TPB>>>(bat);
    k_fc<<<1, 128>>>(fcW, fcb, out);
}

// round 4
// speedup vs baseline: 1.0687x; 1.0687x over previous
#include <cuda_runtime.h>
#include <cuda_fp16.h>
#include <stdint.h>

#define N_NODES 100000
#define N_EDGES 3200000
#define TOT_EDGES (N_EDGES + N_NODES)
#define F_IN 256
#define HID 64
#define C_OUT 2
#define G_GRAPHS 128

#define SCAN_BLK 1024
#define SCAN_NB ((N_NODES + SCAN_BLK - 1) / SCAN_BLK)

// ---------------- scratch: __device__ globals ----------------
__device__ __half g_hxh[(size_t)N_NODES * HID];   // GEMM output (fp16, read by agg)
__device__ float  g_h [(size_t)N_NODES * HID];    // agg output (fp32, read by GEMM2)
__device__ float  g_isq[N_NODES];
__device__ int    g_deg[N_NODES];
__device__ int    g_rowptr[N_NODES + 1];
__device__ int    g_cursor[N_NODES];
__device__ int    g_eidx[TOT_EDGES];
__device__ int    g_bsum[SCAN_NB + 1];
__device__ float  g_pool[G_GRAPHS * HID];
__device__ float  g_pcnt[G_GRAPHS];
__device__ int    g_is64;

// ---------------- dtype detection: odd 32-bit words all zero <=> int64 ----------------
__global__ void k_detect(const int* __restrict__ ei_raw) {
    __shared__ int s_or[256];
    int tid = threadIdx.x;
    int acc = 0;
#pragma unroll
    for (int i = 0; i < 32; i++) {
        int w = 2 * (tid + i * 256) + 1;
        acc |= ei_raw[w];
    }
    s_or[tid] = acc;
    __syncthreads();
    for (int off = 128; off > 0; off >>= 1) {
        if (tid < off) s_or[tid] |= s_or[tid + off];
        __syncthreads();
    }
    if (tid == 0) g_is64 = (s_or[0] == 0) ? 1 : 0;
}

__device__ __forceinline__ int ld_idx(const void* p, size_t i) {
    if (g_is64) return (int)((const long long*)p)[i];
    return ((const int*)p)[i];
}

// ---------------- init ----------------
__global__ void k_init() {
    int i = blockIdx.x * blockDim.x + threadIdx.x;
    if (i < N_NODES) g_deg[i] = 1;
    if (i < G_GRAPHS * HID) g_pool[i] = 0.f;
    if (i < G_GRAPHS) g_pcnt[i] = 0.f;
}

// ---------------- degree histogram over dst ----------------
__global__ void k_deg(const void* __restrict__ ei) {
    int e = blockIdx.x * blockDim.x + threadIdx.x;
    if (e >= N_EDGES) return;
    int d = ld_idx(ei, (size_t)N_EDGES + e);
    atomicAdd(&g_deg[d], 1);
}

// ---------------- scan phase 1: per-block inclusive scan ----------------
__global__ void k_scan1() {
    __shared__ int s[SCAN_BLK];
    int tid = threadIdx.x;
    int i = blockIdx.x * SCAN_BLK + tid;
    int v = (i < N_NODES) ? g_deg[i] : 0;
    s[tid] = v;
    __syncthreads();
    for (int off = 1; off < SCAN_BLK; off <<= 1) {
        int t = (tid >= off) ? s[tid - off] : 0;
        __syncthreads();
        s[tid] += t;
        __syncthreads();
    }
    if (i < N_NODES) g_cursor[i] = s[tid];
    if (tid == SCAN_BLK - 1) g_bsum[blockIdx.x] = s[tid];
}

// ---------------- scan phase 2: parallel scan of 98 block sums ----------------
__global__ void k_scan2() {
    __shared__ int s[128];
    int tid = threadIdx.x;
    int v = (tid < SCAN_NB) ? g_bsum[tid] : 0;
    s[tid] = v;
    __syncthreads();
#pragma unroll
    for (int off = 1; off < 128; off <<= 1) {
        int t = (tid >= off) ? s[tid - off] : 0;
        __syncthreads();
        s[tid] += t;
        __syncthreads();
    }
    if (tid < SCAN_NB) g_bsum[tid] = s[tid] - v;          // exclusive
    if (tid == 127) g_rowptr[N_NODES] = s[127];           // total == TOT_EDGES
}

// ---------------- scan phase 3: finalize rowptr/cursor + isq ----------------
__global__ void k_scan3() {
    int i = blockIdx.x * blockDim.x + threadIdx.x;
    if (i >= N_NODES) return;
    int incl = g_cursor[i] + g_bsum[i / SCAN_BLK];
    g_rowptr[i + 1] = incl;
    int d = g_deg[i];
    g_cursor[i] = incl - d;
    g_isq[i] = rsqrtf((float)d);
    if (i == 0) g_rowptr[0] = 0;
}

// ---------------- fill CSR edge list (incl. self loops) ----------------
__global__ void k_fill(const void* __restrict__ ei) {
    int t = blockIdx.x * blockDim.x + threadIdx.x;
    if (t >= TOT_EDGES) return;
    int s, d;
    if (t < N_EDGES) {
        s = ld_idx(ei, t);
        d = ld_idx(ei, (size_t)N_EDGES + t);
    } else {
        s = d = t - N_EDGES;
    }
    int pos = atomicAdd(&g_cursor[d], 1);
    g_eidx[pos] = s;
}

// ---------------- dense GEMM: g_hxh[N,64] (fp16) = X[N,K] @ W[K,64] ----------------
template <int K, bool FROM_G>
__global__ void k_gemm(const float* __restrict__ Xin, const float* __restrict__ W) {
    __shared__ float sW[32 * 64];
    __shared__ float sX[256 * 33];
    const float* X = FROM_G ? (const float*)g_h : Xin;
    int tid = threadIdx.x;
    int nodeBase = blockIdx.x * 256;
    int node = nodeBase + tid;

    float acc[64];
#pragma unroll
    for (int j = 0; j < 64; j++) acc[j] = 0.f;

    for (int kk = 0; kk < K; kk += 32) {
#pragma unroll
        for (int i = 0; i < 8; i++) {
            int idx = tid + i * 256;
            sW[idx] = W[kk * 64 + idx];
        }
#pragma unroll
        for (int i = 0; i < 32; i++) {
            int idx = tid + i * 256;
            int nl = idx >> 5, kl = idx & 31;
            int n = nodeBase + nl;
            sX[nl * 33 + kl] = (n < N_NODES) ? X[(size_t)n * K + kk + kl] : 0.f;
        }
        __syncthreads();
#pragma unroll 4
        for (int k = 0; k < 32; k++) {
            float xv = sX[tid * 33 + k];
            const float4* w4 = (const float4*)&sW[k * 64];
#pragma unroll
            for (int j = 0; j < 16; j++) {
                float4 w = w4[j];
                acc[4 * j + 0] += xv * w.x;
                acc[4 * j + 1] += xv * w.y;
                acc[4 * j + 2] += xv * w.z;
                acc[4 * j + 3] += xv * w.w;
            }
        }
        __syncthreads();
    }
    if (node < N_NODES) {
        __half2 hh[32];
#pragma unroll
        for (int j = 0; j < 32; j++)
            hh[j] = __floats2half2_rn(acc[2 * j], acc[2 * j + 1]);
        uint4* o4 = (uint4*)&g_hxh[(size_t)node * 64];
        const uint4* src = (const uint4*)hh;
#pragma unroll
        for (int j = 0; j < 8; j++) o4[j] = src[j];
    }
}

// ---------------- pull aggregation: warp/node, fp16 gather, fp32 accumulate ----------------
// optionally fuses mean-pool accumulation (second layer)
template <bool FUSE_POOL>
__global__ void k_agg(const float* __restrict__ bias, const void* __restrict__ batch) {
    int gt = blockIdx.x * blockDim.x + threadIdx.x;
    int node = gt >> 5;
    int lane = gt & 31;
    if (node >= N_NODES) return;

    int r0 = g_rowptr[node];
    int r1 = g_rowptr[node + 1];
    const __half2* h2 = (const __half2*)g_hxh;

    float ax = 0.f, ay = 0.f;
    for (int e = r0; e < r1; e++) {
        int s = g_eidx[e];                         // broadcast
        float w = g_isq[s];                        // broadcast
        float2 v = __half22float2(h2[(size_t)s * 32 + lane]);  // 128B/warp, L2 hit
        ax += w * v.x;
        ay += w * v.y;
    }
    float wd = g_isq[node];
    float ox = fmaxf(ax * wd + bias[2 * lane + 0], 0.f);
    float oy = fmaxf(ay * wd + bias[2 * lane + 1], 0.f);
    ((float2*)g_h)[(size_t)node * 32 + lane] = make_float2(ox, oy);

    if (FUSE_POOL) {
        int g = ld_idx(batch, node);
        atomicAdd(&g_pool[g * 64 + 2 * lane + 0], ox);
        atomicAdd(&g_pool[g * 64 + 2 * lane + 1], oy);
        if (lane == 0) atomicAdd(&g_pcnt[g], 1.f);
    }
}

// ---------------- final FC ----------------
__global__ void k_fc(const float* __restrict__ fcW, const float* __restrict__ fcb,
                     float* __restrict__ out) {
    int g = threadIdx.x;
    if (g >= G_GRAPHS) return;
    float cnt = g_pcnt[g];
    float inv = 1.f / fmaxf(cnt, 1.f);
    float a0 = fcb[0], a1 = fcb[1];
#pragma unroll
    for (int h = 0; h < 64; h++) {
        float p = g_pool[g * 64 + h] * inv;
        a0 += p * fcW[h * 2 + 0];
        a1 += p * fcW[h * 2 + 1];
    }
    out[g * 2 + 0] = a0;
    out[g * 2 + 1] = a1;
}

// ---------------- launch ----------------
extern "C" void kernel_launch(void* const* d_in, const int* in_sizes, int n_in,
                              void* d_out, int out_size) {
    const float* x    = (const float*)d_in[0];
    const void*  ei   = d_in[1];
    const void*  bat  = d_in[2];
    const float* W1   = (const float*)d_in[3];
    const float* b1   = (const float*)d_in[4];
    const float* W2   = (const float*)d_in[5];
    const float* b2   = (const float*)d_in[6];
    const float* fcW  = (const float*)d_in[7];
    const float* fcb  = (const float*)d_in[8];
    float* out = (float*)d_out;

    const int TPB = 256;
    int gN   = (N_NODES + TPB - 1) / TPB;
    int gE   = (N_EDGES + TPB - 1) / TPB;
    int gTOT = (TOT_EDGES + TPB - 1) / TPB;
    int gW   = (N_NODES * 32 + TPB - 1) / TPB;

    k_detect<<<1, 256>>>((const int*)ei);
    k_init<<<gN, TPB>>>();
    k_deg<<<gE, TPB>>>(ei);
    k_scan1<<<SCAN_NB, SCAN_BLK>>>();
    k_scan2<<<1, 128>>>();
    k_scan3<<<gN, TPB>>>();
    k_fill<<<gTOT, TPB>>>(ei);

    k_gemm<F_IN, false><<<gN, TPB>>>(x, W1);          // g_hxh = fp16(x @ W1)
    k_agg<false><<<gW, TPB>>>(b1, nullptr);           // g_h = relu(agg + b1)
    k_gemm<HID, true><<<gN, TPB>>>(nullptr, W2);      // g_hxh = fp16(g_h @ W2)
    k_agg<true><<<gW, TPB>>>(b2, bat);                // g_h = relu(agg + b2), + pool

    k_fc<<<1, 128>>>(fcW, fcb, out);
}

// round 6
// speedup vs baseline: 1.4892x; 1.3935x over previous
#include <cuda_runtime.h>
#include <cuda_fp16.h>
#include <stdint.h>

#define N_NODES 100000
#define N_EDGES 3200000
#define TOT_EDGES (N_EDGES + N_NODES)
#define F_IN 256
#define HID 64
#define C_OUT 2
#define G_GRAPHS 128

#define SCAN_BLK 1024
#define SCAN_NB ((N_NODES + SCAN_BLK - 1) / SCAN_BLK)

// ---------------- scratch: __device__ globals (referenced only in device code) ----------------
__device__ __half g_hxh[(size_t)N_NODES * HID];   // GEMM output (fp16, read by agg)
__device__ float  g_h [(size_t)N_NODES * HID];    // agg output (fp32, read by GEMM2)
__device__ float  g_isq[N_NODES];
__device__ int    g_deg[N_NODES];
__device__ int    g_rowptr[N_NODES + 1];
__device__ int    g_cursor[N_NODES];
__device__ int    g_eidx[TOT_EDGES];
__device__ int    g_bsum[SCAN_NB + 1];
__device__ float  g_pool[G_GRAPHS * HID];
__device__ float  g_pcnt[G_GRAPHS];
__device__ int    g_is64;
__device__ __half g_W1t[64 * 256];                // W1 transposed, fp16: [n][k]
__device__ __half g_W2t[64 * 64];                 // W2 transposed, fp16: [n][k]

// ---------------- dtype detection ----------------
__global__ void k_detect(const int* __restrict__ ei_raw) {
    __shared__ int s_or[256];
    int tid = threadIdx.x;
    int acc = 0;
#pragma unroll
    for (int i = 0; i < 32; i++) {
        int w = 2 * (tid + i * 256) + 1;
        acc |= ei_raw[w];
    }
    s_or[tid] = acc;
    __syncthreads();
    for (int off = 128; off > 0; off >>= 1) {
        if (tid < off) s_or[tid] |= s_or[tid + off];
        __syncthreads();
    }
    if (tid == 0) g_is64 = (s_or[0] == 0) ? 1 : 0;
}

__device__ __forceinline__ int ld_idx(const void* p, size_t i) {
    if (g_is64) return (int)((const long long*)p)[i];
    return ((const int*)p)[i];
}

// ---------------- init ----------------
__global__ void k_init() {
    int i = blockIdx.x * blockDim.x + threadIdx.x;
    if (i < N_NODES) g_deg[i] = 1;
    if (i < G_GRAPHS * HID) g_pool[i] = 0.f;
    if (i < G_GRAPHS) g_pcnt[i] = 0.f;
}

// ---------------- W transpose + fp16 convert (one-time, tiny) ----------------
__global__ void k_wt(const float* __restrict__ W1, const float* __restrict__ W2) {
    int i = blockIdx.x * blockDim.x + threadIdx.x;
    if (i < 64 * 256) {
        int n = i >> 8, k = i & 255;
        g_W1t[i] = __float2half_rn(W1[k * 64 + n]);
    }
    if (i < 64 * 64) {
        int n = i >> 6, k = i & 63;
        g_W2t[i] = __float2half_rn(W2[k * 64 + n]);
    }
}

// ---------------- degree histogram over dst ----------------
__global__ void k_deg(const void* __restrict__ ei) {
    int e = blockIdx.x * blockDim.x + threadIdx.x;
    if (e >= N_EDGES) return;
    int d = ld_idx(ei, (size_t)N_EDGES + e);
    atomicAdd(&g_deg[d], 1);
}

// ---------------- scan phase 1 ----------------
__global__ void k_scan1() {
    __shared__ int s[SCAN_BLK];
    int tid = threadIdx.x;
    int i = blockIdx.x * SCAN_BLK + tid;
    int v = (i < N_NODES) ? g_deg[i] : 0;
    s[tid] = v;
    __syncthreads();
    for (int off = 1; off < SCAN_BLK; off <<= 1) {
        int t = (tid >= off) ? s[tid - off] : 0;
        __syncthreads();
        s[tid] += t;
        __syncthreads();
    }
    if (i < N_NODES) g_cursor[i] = s[tid];
    if (tid == SCAN_BLK - 1) g_bsum[blockIdx.x] = s[tid];
}

// ---------------- scan phase 2 ----------------
__global__ void k_scan2() {
    __shared__ int s[128];
    int tid = threadIdx.x;
    int v = (tid < SCAN_NB) ? g_bsum[tid] : 0;
    s[tid] = v;
    __syncthreads();
#pragma unroll
    for (int off = 1; off < 128; off <<= 1) {
        int t = (tid >= off) ? s[tid - off] : 0;
        __syncthreads();
        s[tid] += t;
        __syncthreads();
    }
    if (tid < SCAN_NB) g_bsum[tid] = s[tid] - v;
    if (tid == 127) g_rowptr[N_NODES] = s[127];
}

// ---------------- scan phase 3 ----------------
__global__ void k_scan3() {
    int i = blockIdx.x * blockDim.x + threadIdx.x;
    if (i >= N_NODES) return;
    int incl = g_cursor[i] + g_bsum[i / SCAN_BLK];
    g_rowptr[i + 1] = incl;
    int d = g_deg[i];
    g_cursor[i] = incl - d;
    g_isq[i] = rsqrtf((float)d);
    if (i == 0) g_rowptr[0] = 0;
}

// ---------------- fill CSR ----------------
__global__ void k_fill(const void* __restrict__ ei) {
    int t = blockIdx.x * blockDim.x + threadIdx.x;
    if (t >= TOT_EDGES) return;
    int s, d;
    if (t < N_EDGES) {
        s = ld_idx(ei, t);
        d = ld_idx(ei, (size_t)N_EDGES + t);
    } else {
        s = d = t - N_EDGES;
    }
    int pos = atomicAdd(&g_cursor[d], 1);
    g_eidx[pos] = s;
}

// ---------------- tensor-core GEMM: g_hxh[N,64](fp16) = X[N,K] @ W[K,64] ----------------
// 256 threads = 8 warps; block tile M=128, N=64; mma.m16n8k16 fp16->fp32.
// LAYER selects both X source and weight symbol inside device code.
template <int K, int LAYER>
__global__ void k_gemm_mma(const float* __restrict__ Xin) {
    constexpr int CK = 64;                    // K chunk staged per iteration
    constexpr int APAD = 72;                  // halves per sX row (72/2=36 -> conflict-free)
    constexpr int WPAD = K + 8;               // halves per sWt row ((K+8)/2 % 32 == 4)
    __shared__ __half sX[128 * APAD];         // 18 KB
    __shared__ __half sWt[64 * WPAD];         // 33.8 KB (K=256) / 9.2 KB (K=64)

    const float*  X  = (LAYER == 1) ? Xin : (const float*)g_h;
    const __half* Wt = (LAYER == 1) ? g_W1t : g_W2t;
    int tid = threadIdx.x;
    int wid = tid >> 5, lane = tid & 31;
    int g = lane >> 2, tig = lane & 3;
    int nodeBase = blockIdx.x * 128;

    // copy transposed fp16 weights into padded smem rows
    for (int i = tid; i < 64 * (K / 2); i += 256) {
        int n = i / (K / 2), kw = i % (K / 2);
        ((uint32_t*)sWt)[n * (WPAD / 2) + kw] = ((const uint32_t*)Wt)[n * (K / 2) + kw];
    }

    float acc[8][4];
#pragma unroll
    for (int nt = 0; nt < 8; nt++)
#pragma unroll
        for (int j = 0; j < 4; j++) acc[nt][j] = 0.f;

    for (int kk = 0; kk < K; kk += CK) {
        // stage X chunk [128 x CK] as fp16
        for (int i = tid; i < 128 * (CK / 2); i += 256) {
            int row = i >> 5;                 // CK/2 == 32
            int c2 = i & 31;
            int node = nodeBase + row;
            float2 v = (node < N_NODES)
                ? *(const float2*)&X[(size_t)node * K + kk + c2 * 2]
                : make_float2(0.f, 0.f);
            ((__half2*)sX)[row * (APAD / 2) + c2] = __floats2half2_rn(v.x, v.y);
        }
        __syncthreads();

        int mrow = wid * 16;
#pragma unroll
        for (int kt = 0; kt < CK / 16; kt++) {
            int k0 = kt * 16;
            uint32_t a0 = *(const uint32_t*)&sX[(mrow + g    ) * APAD + k0     + 2 * tig];
            uint32_t a1 = *(const uint32_t*)&sX[(mrow + g + 8) * APAD + k0     + 2 * tig];
            uint32_t a2 = *(const uint32_t*)&sX[(mrow + g    ) * APAD + k0 + 8 + 2 * tig];
            uint32_t a3 = *(const uint32_t*)&sX[(mrow + g + 8) * APAD + k0 + 8 + 2 * tig];
#pragma unroll
            for (int nt = 0; nt < 8; nt++) {
                uint32_t b0 = *(const uint32_t*)&sWt[(nt * 8 + g) * WPAD + kk + k0     + 2 * tig];
                uint32_t b1 = *(const uint32_t*)&sWt[(nt * 8 + g) * WPAD + kk + k0 + 8 + 2 * tig];
                asm volatile(
                    "mma.sync.aligned.m16n8k16.row.col.f32.f16.f16.f32 "
                    "{%0,%1,%2,%3}, {%4,%5,%6,%7}, {%8,%9}, {%0,%1,%2,%3};\n"
                    : "+f"(acc[nt][0]), "+f"(acc[nt][1]), "+f"(acc[nt][2]), "+f"(acc[nt][3])
                    : "r"(a0), "r"(a1), "r"(a2), "r"(a3), "r"(b0), "r"(b1));
            }
        }
        __syncthreads();
    }

    // write fp16 results: c0,c1 -> row (mrow+g), cols nt*8+2tig; c2,c3 -> row+8
    int r0 = nodeBase + wid * 16 + g;
#pragma unroll
    for (int nt = 0; nt < 8; nt++) {
        if (r0 < N_NODES)
            *(__half2*)&g_hxh[(size_t)r0 * 64 + nt * 8 + 2 * tig] =
                __floats2half2_rn(acc[nt][0], acc[nt][1]);
        if (r0 + 8 < N_NODES)
            *(__half2*)&g_hxh[(size_t)(r0 + 8) * 64 + nt * 8 + 2 * tig] =
                __floats2half2_rn(acc[nt][2], acc[nt][3]);
    }
}

// ---------------- pull aggregation: warp/node, fp16 gather, fp32 accumulate ----------------
template <bool FUSE_POOL>
__global__ void k_agg(const float* __restrict__ bias, const void* __restrict__ batch) {
    int gt = blockIdx.x * blockDim.x + threadIdx.x;
    int node = gt >> 5;
    int lane = gt & 31;
    if (node >= N_NODES) return;

    int r0 = g_rowptr[node];
    int r1 = g_rowptr[node + 1];
    const __half2* h2 = (const __half2*)g_hxh;

    float ax = 0.f, ay = 0.f;
    for (int e = r0; e < r1; e++) {
        int s = g_eidx[e];
        float w = g_isq[s];
        float2 v = __half22float2(h2[(size_t)s * 32 + lane]);
        ax += w * v.x;
        ay += w * v.y;
    }
    float wd = g_isq[node];
    float ox = fmaxf(ax * wd + bias[2 * lane + 0], 0.f);
    float oy = fmaxf(ay * wd + bias[2 * lane + 1], 0.f);
    ((float2*)g_h)[(size_t)node * 32 + lane] = make_float2(ox, oy);

    if (FUSE_POOL) {
        int gph = ld_idx(batch, node);
        atomicAdd(&g_pool[gph * 64 + 2 * lane + 0], ox);
        atomicAdd(&g_pool[gph * 64 + 2 * lane + 1], oy);
        if (lane == 0) atomicAdd(&g_pcnt[gph], 1.f);
    }
}

// ---------------- final FC ----------------
__global__ void k_fc(const float* __restrict__ fcW, const float* __restrict__ fcb,
                     float* __restrict__ out) {
    int g = threadIdx.x;
    if (g >= G_GRAPHS) return;
    float cnt = g_pcnt[g];
    float inv = 1.f / fmaxf(cnt, 1.f);
    float a0 = fcb[0], a1 = fcb[1];
#pragma unroll
    for (int h = 0; h < 64; h++) {
        float p = g_pool[g * 64 + h] * inv;
        a0 += p * fcW[h * 2 + 0];
        a1 += p * fcW[h * 2 + 1];
    }
    out[g * 2 + 0] = a0;
    out[g * 2 + 1] = a1;
}

// ---------------- launch ----------------
extern "C" void kernel_launch(void* const* d_in, const int* in_sizes, int n_in,
                              void* d_out, int out_size) {
    const float* x    = (const float*)d_in[0];
    const void*  ei   = d_in[1];
    const void*  bat  = d_in[2];
    const float* W1   = (const float*)d_in[3];
    const float* b1   = (const float*)d_in[4];
    const float* W2   = (const float*)d_in[5];
    const float* b2   = (const float*)d_in[6];
    const float* fcW  = (const float*)d_in[7];
    const float* fcb  = (const float*)d_in[8];
    float* out = (float*)d_out;

    const int TPB = 256;
    int gN   = (N_NODES + TPB - 1) / TPB;
    int gE   = (N_EDGES + TPB - 1) / TPB;
    int gTOT = (TOT_EDGES + TPB - 1) / TPB;
    int gW   = (N_NODES * 32 + TPB - 1) / TPB;
    int gM   = (N_NODES + 127) / 128;                // mma-gemm grid

    k_detect<<<1, 256>>>((const int*)ei);
    k_init<<<gN, TPB>>>();
    k_wt<<<64, 256>>>(W1, W2);
    k_deg<<<gE, TPB>>>(ei);
    k_scan1<<<SCAN_NB, SCAN_BLK>>>();
    k_scan2<<<1, 128>>>();
    k_scan3<<<gN, TPB>>>();
    k_fill<<<gTOT, TPB>>>(ei);

    k_gemm_mma<F_IN, 1><<<gM, TPB>>>(x);              // g_hxh = fp16(x @ W1)
    k_agg<false><<<gW, TPB>>>(b1, nullptr);           // g_h = relu(agg + b1)
    k_gemm_mma<HID, 2><<<gM, TPB>>>(nullptr);         // g_hxh = fp16(g_h @ W2)
    k_agg<true><<<gW, TPB>>>(b2, bat);                // g_h = relu(agg + b2) + pool

    k_fc<<<1, 128>>>(fcW, fcb, out);
}